// round 9
// baseline (speedup 1.0000x reference)
#include <cuda_runtime.h>
#include <cuda_fp16.h>
#include <cstdint>

#define NN 100000
#define NE 1600000
#define SCAN_TILE 1024
#define SCAN_NB ((NN + SCAN_TILE - 1) / SCAN_TILE)   // 98

#define APAD 136   // As row stride (halves)
#define WPAD 40    // Wts row stride (halves)

// m16n8k16 fp16 MMA, fp32 accumulate (sm_80+ PTX, works on compute_103)
#define MMA16816(c0, c1, c2, c3, a0, a1, a2, a3, b0, b1) \
    asm volatile("mma.sync.aligned.m16n8k16.row.col.f32.f16.f16.f32 " \
        "{%0,%1,%2,%3}, {%4,%5,%6,%7}, {%8,%9}, {%0,%1,%2,%3};" \
        : "+f"(c0), "+f"(c1), "+f"(c2), "+f"(c3) \
        : "r"(a0), "r"(a1), "r"(a2), "r"(a3), "r"(b0), "r"(b1))

// ---------------- device scratch ----------------
__device__ int     g_deg_in[NN];
__device__ int     g_deg_out[NN];
__device__ int     g_cursor[NN];
__device__ float   g_norm_src[NN];
__device__ float   g_norm_dst[NN];
__device__ int     g_row_ptr[NN + 1];
__device__ int     g_csr_src[NE];
__device__ int     g_blk_sum[SCAN_NB];
__device__ int     g_blk_off[SCAN_NB];
__device__ __half2 g_emb_h[(size_t)NN * 64];   // emb * norm_src, fp16
__device__ __half2 g_t_h[(size_t)NN * 32];     // (h1@W2)*norm_src, fp16

// ---------------- setup ----------------
__global__ void k_zero(int n) {
    int i = blockIdx.x * blockDim.x + threadIdx.x;
    if (i < n) { g_deg_in[i] = 0; g_deg_out[i] = 0; g_cursor[i] = 0; }
}

// 2 edges per thread, int2 loads
__global__ void k_degree(const int* __restrict__ src,
                         const int* __restrict__ dst, int e2, int e) {
    int i = blockIdx.x * blockDim.x + threadIdx.x;
    if (i < e2) {
        int2 s = ((const int2*)src)[i];
        int2 d = ((const int2*)dst)[i];
        if ((unsigned)s.x < NN) atomicAdd(&g_deg_out[s.x], 1);
        if ((unsigned)s.y < NN) atomicAdd(&g_deg_out[s.y], 1);
        if ((unsigned)d.x < NN) atomicAdd(&g_deg_in[d.x], 1);
        if ((unsigned)d.y < NN) atomicAdd(&g_deg_in[d.y], 1);
    } else if (i == e2 && (e & 1)) {
        int s = src[e - 1], d = dst[e - 1];
        if ((unsigned)s < NN) atomicAdd(&g_deg_out[s], 1);
        if ((unsigned)d < NN) atomicAdd(&g_deg_in[d], 1);
    }
}

// emb * norm_src -> half2; 8 floats per thread
__global__ void k_prep(const float* __restrict__ emb, int n16) {
    int i = blockIdx.x * blockDim.x + threadIdx.x;   // one per 8 feats
    if (i < n16) {
        int r = i >> 4;
        float4 v0 = ((const float4*)emb)[2 * i];
        float4 v1 = ((const float4*)emb)[2 * i + 1];
        float ns = g_norm_src[r];
        uint4 o;
        *(__half2*)&o.x = __floats2half2_rn(v0.x * ns, v0.y * ns);
        *(__half2*)&o.y = __floats2half2_rn(v0.z * ns, v0.w * ns);
        *(__half2*)&o.z = __floats2half2_rn(v1.x * ns, v1.y * ns);
        *(__half2*)&o.w = __floats2half2_rn(v1.z * ns, v1.w * ns);
        ((uint4*)g_emb_h)[i] = o;
    }
}

// ---------------- scan phase 1 + norm computation (fused) ----------------
__global__ void __launch_bounds__(256)
k_scan_partial(int n) {
    __shared__ int sm[256];
    int t = threadIdx.x;
    int base = blockIdx.x * SCAN_TILE + t * 4;
    int s = 0;
#pragma unroll
    for (int j = 0; j < 4; j++) {
        int i = base + j;
        if (i < n) {
            int din = g_deg_in[i];
            s += din;
            int dout = g_deg_out[i];
            if (dout < 1) dout = 1;
            if (din  < 1) din  = 1;
            g_norm_src[i] = rsqrtf((float)dout);
            g_norm_dst[i] = rsqrtf((float)din);
        }
    }
    sm[t] = s;
    __syncthreads();
    for (int off = 128; off > 0; off >>= 1) {
        if (t < off) sm[t] += sm[t + off];
        __syncthreads();
    }
    if (t == 0) g_blk_sum[blockIdx.x] = sm[0];
}

__global__ void __launch_bounds__(128)
k_scan_blk(int n, int e) {
    __shared__ int sm[128];
    int t = threadIdx.x;
    int v = (t < SCAN_NB) ? g_blk_sum[t] : 0;
    sm[t] = v;
    __syncthreads();
    for (int off = 1; off < 128; off <<= 1) {
        int add = 0;
        if (t >= off) add = sm[t - off];
        __syncthreads();
        sm[t] += add;
        __syncthreads();
    }
    if (t < SCAN_NB) g_blk_off[t] = sm[t] - v;
    if (t == 0) g_row_ptr[n] = e;
}

__global__ void __launch_bounds__(256)
k_scan_final(int n) {
    __shared__ int sm[256];
    int t = threadIdx.x;
    int base = blockIdx.x * SCAN_TILE + t * 4;
    int d[4];
    int s = 0;
#pragma unroll
    for (int j = 0; j < 4; j++) {
        int i = base + j;
        d[j] = (i < n) ? g_deg_in[i] : 0;
        s += d[j];
    }
    sm[t] = s;
    __syncthreads();
    for (int off = 1; off < 256; off <<= 1) {
        int add = 0;
        if (t >= off) add = sm[t - off];
        __syncthreads();
        sm[t] += add;
        __syncthreads();
    }
    int run = g_blk_off[blockIdx.x] + sm[t] - s;
#pragma unroll
    for (int j = 0; j < 4; j++) {
        int i = base + j;
        if (i < n) g_row_ptr[i] = run;
        run += d[j];
    }
}

__global__ void k_fill(const int* __restrict__ src,
                       const int* __restrict__ dst, int e) {
    int i = blockIdx.x * blockDim.x + threadIdx.x;
    if (i < e) {
        int s = src[i];
        int d = dst[i];
        if ((unsigned)d < NN && (unsigned)s < NN) {
            int pos = g_row_ptr[d] + atomicAdd(&g_cursor[d], 1);
            g_csr_src[pos] = s;
        }
    }
}

// ---------------- fused SpMM1 + GEMM via HMMA ----------------
// block = 256 thr (8 warps), 128 rows; warp w gathers + computes rows 16w..16w+15.
// gather: agg = (sum_{s->d} emb_h[s]) * norm_dst[d]  -> fp16 -> As (warp-local rows)
// phase1: h1 = relu(As @ W1 + b1) -> fp16 back into As
// phase2: t  = (h1 @ W2) * norm_src -> g_t_h
__global__ void __launch_bounds__(256)
k_gemm_fused(const float* __restrict__ W1, const float* __restrict__ b1,
             const float* __restrict__ W2, int n) {
    __shared__ __half As[128 * APAD];    // 34.8KB
    __shared__ __half Wts[128 * WPAD];   // 10.2KB, [n][k] transposed chunks
    __shared__ float b1s[128];

    const int tid = threadIdx.x;
    const int lane = tid & 31;
    const int wid = tid >> 5;
    const int row0 = blockIdx.x * 128;
    const int m0 = wid * 16;
    const int r = lane >> 2;          // 0..7
    const int qc = (lane & 3) * 2;    // 0,2,4,6

    if (tid < 128) b1s[tid] = b1[tid];

    // ---- gather (SpMM1) into As: warp per row, 16 rows per warp ----
    {
        const uint2* eh = (const uint2*)g_emb_h;   // row = 32 uint2
        for (int rr = 0; rr < 16; rr++) {
            int gr = row0 + m0 + rr;
            float4 acc = make_float4(0.f, 0.f, 0.f, 0.f);
            if (gr < n) {
                int beg = g_row_ptr[gr];
                int end = g_row_ptr[gr + 1];
                int ed = beg;
                for (; ed + 3 < end; ed += 4) {
                    int s0 = g_csr_src[ed];
                    int s1 = g_csr_src[ed + 1];
                    int s2 = g_csr_src[ed + 2];
                    int s3 = g_csr_src[ed + 3];
                    uint2 v0 = eh[(size_t)s0 * 32 + lane];
                    uint2 v1 = eh[(size_t)s1 * 32 + lane];
                    uint2 v2 = eh[(size_t)s2 * 32 + lane];
                    uint2 v3 = eh[(size_t)s3 * 32 + lane];
                    float2 a0 = __half22float2(*(__half2*)&v0.x), c0 = __half22float2(*(__half2*)&v0.y);
                    float2 a1 = __half22float2(*(__half2*)&v1.x), c1 = __half22float2(*(__half2*)&v1.y);
                    float2 a2 = __half22float2(*(__half2*)&v2.x), c2 = __half22float2(*(__half2*)&v2.y);
                    float2 a3 = __half22float2(*(__half2*)&v3.x), c3 = __half22float2(*(__half2*)&v3.y);
                    acc.x += (a0.x + a1.x) + (a2.x + a3.x);
                    acc.y += (a0.y + a1.y) + (a2.y + a3.y);
                    acc.z += (c0.x + c1.x) + (c2.x + c3.x);
                    acc.w += (c0.y + c1.y) + (c2.y + c3.y);
                }
                for (; ed < end; ed++) {
                    int s0 = g_csr_src[ed];
                    uint2 v0 = eh[(size_t)s0 * 32 + lane];
                    float2 a0 = __half22float2(*(__half2*)&v0.x);
                    float2 c0 = __half22float2(*(__half2*)&v0.y);
                    acc.x += a0.x; acc.y += a0.y; acc.z += c0.x; acc.w += c0.y;
                }
                float nd = g_norm_dst[gr];
                acc.x *= nd; acc.y *= nd; acc.z *= nd; acc.w *= nd;
            }
            uint2 o;
            *(__half2*)&o.x = __floats2half2_rn(acc.x, acc.y);
            *(__half2*)&o.y = __floats2half2_rn(acc.z, acc.w);
            *(uint2*)&As[(m0 + rr) * APAD + lane * 4] = o;
        }
    }
    // no block sync needed for As: each warp's MMA A-fragments read only its own rows

    // ---- phase 1: 16x128 per warp, K=128 ----
    float acc[16][4];
#pragma unroll
    for (int t2 = 0; t2 < 16; t2++)
#pragma unroll
        for (int j = 0; j < 4; j++) acc[t2][j] = 0.f;

    for (int kc = 0; kc < 4; kc++) {
        __syncthreads();
        for (int i = tid; i < 32 * 128; i += 256) {
            int kl = i >> 7, nn = i & 127;
            Wts[nn * WPAD + kl] = __float2half(W1[(kc * 32 + kl) * 128 + nn]);
        }
        __syncthreads();
#pragma unroll
        for (int ks = 0; ks < 2; ks++) {
            int kb = kc * 32 + ks * 16;
            uint32_t a0 = *(uint32_t*)&As[(m0 + r) * APAD + kb + qc];
            uint32_t a1 = *(uint32_t*)&As[(m0 + r + 8) * APAD + kb + qc];
            uint32_t a2 = *(uint32_t*)&As[(m0 + r) * APAD + kb + qc + 8];
            uint32_t a3 = *(uint32_t*)&As[(m0 + r + 8) * APAD + kb + qc + 8];
            int kw = ks * 16;
#pragma unroll
            for (int nt = 0; nt < 16; nt++) {
                uint32_t b0 = *(uint32_t*)&Wts[(nt * 8 + r) * WPAD + kw + qc];
                uint32_t b1f = *(uint32_t*)&Wts[(nt * 8 + r) * WPAD + kw + qc + 8];
                MMA16816(acc[nt][0], acc[nt][1], acc[nt][2], acc[nt][3],
                         a0, a1, a2, a3, b0, b1f);
            }
        }
    }

    // epilogue 1: relu + bias, write h1 fp16 into As (own rows only)
#pragma unroll
    for (int nt = 0; nt < 16; nt++) {
        int c = nt * 8 + qc;
        float x0 = fmaxf(acc[nt][0] + b1s[c],     0.f);
        float x1 = fmaxf(acc[nt][1] + b1s[c + 1], 0.f);
        float x2 = fmaxf(acc[nt][2] + b1s[c],     0.f);
        float x3 = fmaxf(acc[nt][3] + b1s[c + 1], 0.f);
        *(__half2*)&As[(m0 + r) * APAD + c]     = __floats2half2_rn(x0, x1);
        *(__half2*)&As[(m0 + r + 8) * APAD + c] = __floats2half2_rn(x2, x3);
    }

    // ---- phase 2: 16x64 per warp, K=128 ----
    float acc2[8][4];
#pragma unroll
    for (int t2 = 0; t2 < 8; t2++)
#pragma unroll
        for (int j = 0; j < 4; j++) acc2[t2][j] = 0.f;

    for (int kc = 0; kc < 4; kc++) {
        __syncthreads();
        for (int i = tid; i < 32 * 64; i += 256) {
            int kl = i >> 6, nn = i & 63;
            Wts[nn * WPAD + kl] = __float2half(W2[(kc * 32 + kl) * 64 + nn]);
        }
        __syncthreads();
#pragma unroll
        for (int ks = 0; ks < 2; ks++) {
            int kb = kc * 32 + ks * 16;
            uint32_t a0 = *(uint32_t*)&As[(m0 + r) * APAD + kb + qc];
            uint32_t a1 = *(uint32_t*)&As[(m0 + r + 8) * APAD + kb + qc];
            uint32_t a2 = *(uint32_t*)&As[(m0 + r) * APAD + kb + qc + 8];
            uint32_t a3 = *(uint32_t*)&As[(m0 + r + 8) * APAD + kb + qc + 8];
            int kw = ks * 16;
#pragma unroll
            for (int nt = 0; nt < 8; nt++) {
                uint32_t b0 = *(uint32_t*)&Wts[(nt * 8 + r) * WPAD + kw + qc];
                uint32_t b1f = *(uint32_t*)&Wts[(nt * 8 + r) * WPAD + kw + qc + 8];
                MMA16816(acc2[nt][0], acc2[nt][1], acc2[nt][2], acc2[nt][3],
                         a0, a1, a2, a3, b0, b1f);
            }
        }
    }

    // epilogue 2: * norm_src, fp16 store
    {
        int gr0 = row0 + m0 + r;
        int gr1 = gr0 + 8;
        float ns0 = (gr0 < n) ? g_norm_src[gr0] : 0.f;
        float ns1 = (gr1 < n) ? g_norm_src[gr1] : 0.f;
#pragma unroll
        for (int nt = 0; nt < 8; nt++) {
            int c = nt * 8 + qc;   // even
            if (gr0 < n)
                g_t_h[(size_t)gr0 * 32 + (c >> 1)] =
                    __floats2half2_rn(acc2[nt][0] * ns0, acc2[nt][1] * ns0);
            if (gr1 < n)
                g_t_h[(size_t)gr1 * 32 + (c >> 1)] =
                    __floats2half2_rn(acc2[nt][2] * ns1, acc2[nt][3] * ns1);
        }
    }
}

// ---------------- SpMM 2 (fp16 gather, 4-edge unroll) ----------------
__global__ void k_spmm2(const float* __restrict__ b2, float* __restrict__ out, int n) {
    int w = (blockIdx.x * blockDim.x + threadIdx.x) >> 5;
    int lane = threadIdx.x & 31;
    if (w >= n) return;
    int beg = g_row_ptr[w];
    int end = g_row_ptr[w + 1];
    float2 acc = make_float2(0.f, 0.f);
    int ed = beg;
    for (; ed + 3 < end; ed += 4) {
        int s0 = g_csr_src[ed];
        int s1 = g_csr_src[ed + 1];
        int s2 = g_csr_src[ed + 2];
        int s3 = g_csr_src[ed + 3];
        float2 v0 = __half22float2(g_t_h[(size_t)s0 * 32 + lane]);
        float2 v1 = __half22float2(g_t_h[(size_t)s1 * 32 + lane]);
        float2 v2 = __half22float2(g_t_h[(size_t)s2 * 32 + lane]);
        float2 v3 = __half22float2(g_t_h[(size_t)s3 * 32 + lane]);
        acc.x += (v0.x + v1.x) + (v2.x + v3.x);
        acc.y += (v0.y + v1.y) + (v2.y + v3.y);
    }
    for (; ed < end; ed++) {
        int s0 = g_csr_src[ed];
        float2 v0 = __half22float2(g_t_h[(size_t)s0 * 32 + lane]);
        acc.x += v0.x;
        acc.y += v0.y;
    }
    float nd = g_norm_dst[w];
    float2 bb = ((const float2*)b2)[lane];
    float2 o;
    o.x = fmaf(acc.x, nd, bb.x);
    o.y = fmaf(acc.y, nd, bb.y);
    ((float2*)out)[(size_t)w * 32 + lane] = o;
}

// ---------------- launch ----------------
extern "C" void kernel_launch(void* const* d_in, const int* in_sizes, int n_in,
                              void* d_out, int out_size) {
    const int* src = (const int*)d_in[1];
    const int* dst = (const int*)d_in[2];
    const float* emb = (const float*)d_in[3];
    const float* W1  = (const float*)d_in[4];
    const float* b1  = (const float*)d_in[5];
    const float* W2  = (const float*)d_in[6];
    const float* b2  = (const float*)d_in[7];
    float* out = (float*)d_out;

    const int n = in_sizes[0];
    const int e = in_sizes[1];
    const int e2 = e >> 1;

    k_zero<<<(n + 255) / 256, 256>>>(n);
    k_degree<<<(e2 + 256) / 256, 256>>>(src, dst, e2, e);
    k_scan_partial<<<SCAN_NB, 256>>>(n);     // also computes norms
    k_prep<<<(n * 16 + 255) / 256, 256>>>(emb, n * 16);
    k_scan_blk<<<1, 128>>>(n, e);
    k_scan_final<<<SCAN_NB, 256>>>(n);
    k_fill<<<(e + 255) / 256, 256>>>(src, dst, e);

    k_gemm_fused<<<(n + 127) / 128, 256>>>(W1, b1, W2, n);
    k_spmm2<<<(n * 32 + 255) / 256, 256>>>(b2, out, n);
}

// round 10
// speedup vs baseline: 1.2106x; 1.2106x over previous
#include <cuda_runtime.h>
#include <cuda_fp16.h>
#include <cstdint>

#define NN 100000
#define NE 1600000
#define SCAN_TILE 1024
#define SCAN_NB ((NN + SCAN_TILE - 1) / SCAN_TILE)   // 98

#define APAD 136   // As row stride (halves)
#define WPAD 40    // Wts row stride (halves)

// m16n8k16 fp16 MMA, fp32 accumulate (sm_80+ PTX, works on compute_103)
#define MMA16816(c0, c1, c2, c3, a0, a1, a2, a3, b0, b1) \
    asm volatile("mma.sync.aligned.m16n8k16.row.col.f32.f16.f16.f32 " \
        "{%0,%1,%2,%3}, {%4,%5,%6,%7}, {%8,%9}, {%0,%1,%2,%3};" \
        : "+f"(c0), "+f"(c1), "+f"(c2), "+f"(c3) \
        : "r"(a0), "r"(a1), "r"(a2), "r"(a3), "r"(b0), "r"(b1))

// ---------------- device scratch ----------------
__device__ int     g_deg_in[NN];
__device__ int     g_deg_out[NN];
__device__ int     g_cursor[NN];
__device__ float   g_norm_src[NN];
__device__ float   g_norm_dst[NN];
__device__ int     g_row_ptr[NN + 1];
__device__ int     g_csr_src[NE];
__device__ int     g_blk_sum[SCAN_NB];
__device__ int     g_blk_off[SCAN_NB];
__device__ __half2 g_emb_h[(size_t)NN * 64];   // emb * norm_src, fp16
__device__ __half2 g_agg_h[(size_t)NN * 64];   // spmm1 result, fp16
__device__ __half2 g_t_h[(size_t)NN * 32];     // (h1@W2)*norm_src, fp16

// ---------------- setup ----------------
__global__ void k_zero(int n) {
    int i = blockIdx.x * blockDim.x + threadIdx.x;
    if (i < n) { g_deg_in[i] = 0; g_deg_out[i] = 0; g_cursor[i] = 0; }
}

// 2 edges per thread, int2 loads
__global__ void k_degree(const int* __restrict__ src,
                         const int* __restrict__ dst, int e2, int e) {
    int i = blockIdx.x * blockDim.x + threadIdx.x;
    if (i < e2) {
        int2 s = ((const int2*)src)[i];
        int2 d = ((const int2*)dst)[i];
        if ((unsigned)s.x < NN) atomicAdd(&g_deg_out[s.x], 1);
        if ((unsigned)s.y < NN) atomicAdd(&g_deg_out[s.y], 1);
        if ((unsigned)d.x < NN) atomicAdd(&g_deg_in[d.x], 1);
        if ((unsigned)d.y < NN) atomicAdd(&g_deg_in[d.y], 1);
    } else if (i == e2 && (e & 1)) {
        int s = src[e - 1], d = dst[e - 1];
        if ((unsigned)s < NN) atomicAdd(&g_deg_out[s], 1);
        if ((unsigned)d < NN) atomicAdd(&g_deg_in[d], 1);
    }
}

// emb * norm_src -> half2; 8 floats per thread
__global__ void k_prep(const float* __restrict__ emb, int n16) {
    int i = blockIdx.x * blockDim.x + threadIdx.x;   // one per 8 feats
    if (i < n16) {
        int r = i >> 4;
        float4 v0 = ((const float4*)emb)[2 * i];
        float4 v1 = ((const float4*)emb)[2 * i + 1];
        float ns = g_norm_src[r];
        uint4 o;
        *(__half2*)&o.x = __floats2half2_rn(v0.x * ns, v0.y * ns);
        *(__half2*)&o.y = __floats2half2_rn(v0.z * ns, v0.w * ns);
        *(__half2*)&o.z = __floats2half2_rn(v1.x * ns, v1.y * ns);
        *(__half2*)&o.w = __floats2half2_rn(v1.z * ns, v1.w * ns);
        ((uint4*)g_emb_h)[i] = o;
    }
}

// ---------------- scan phase 1 + norm computation (fused) ----------------
__global__ void __launch_bounds__(256)
k_scan_partial(int n) {
    __shared__ int sm[256];
    int t = threadIdx.x;
    int base = blockIdx.x * SCAN_TILE + t * 4;
    int s = 0;
#pragma unroll
    for (int j = 0; j < 4; j++) {
        int i = base + j;
        if (i < n) {
            int din = g_deg_in[i];
            s += din;
            int dout = g_deg_out[i];
            if (dout < 1) dout = 1;
            if (din  < 1) din  = 1;
            g_norm_src[i] = rsqrtf((float)dout);
            g_norm_dst[i] = rsqrtf((float)din);
        }
    }
    sm[t] = s;
    __syncthreads();
    for (int off = 128; off > 0; off >>= 1) {
        if (t < off) sm[t] += sm[t + off];
        __syncthreads();
    }
    if (t == 0) g_blk_sum[blockIdx.x] = sm[0];
}

__global__ void __launch_bounds__(128)
k_scan_blk(int n, int e) {
    __shared__ int sm[128];
    int t = threadIdx.x;
    int v = (t < SCAN_NB) ? g_blk_sum[t] : 0;
    sm[t] = v;
    __syncthreads();
    for (int off = 1; off < 128; off <<= 1) {
        int add = 0;
        if (t >= off) add = sm[t - off];
        __syncthreads();
        sm[t] += add;
        __syncthreads();
    }
    if (t < SCAN_NB) g_blk_off[t] = sm[t] - v;
    if (t == 0) g_row_ptr[n] = e;
}

__global__ void __launch_bounds__(256)
k_scan_final(int n) {
    __shared__ int sm[256];
    int t = threadIdx.x;
    int base = blockIdx.x * SCAN_TILE + t * 4;
    int d[4];
    int s = 0;
#pragma unroll
    for (int j = 0; j < 4; j++) {
        int i = base + j;
        d[j] = (i < n) ? g_deg_in[i] : 0;
        s += d[j];
    }
    sm[t] = s;
    __syncthreads();
    for (int off = 1; off < 256; off <<= 1) {
        int add = 0;
        if (t >= off) add = sm[t - off];
        __syncthreads();
        sm[t] += add;
        __syncthreads();
    }
    int run = g_blk_off[blockIdx.x] + sm[t] - s;
#pragma unroll
    for (int j = 0; j < 4; j++) {
        int i = base + j;
        if (i < n) g_row_ptr[i] = run;
        run += d[j];
    }
}

// 2 edges per thread, int2 loads
__global__ void k_fill(const int* __restrict__ src,
                       const int* __restrict__ dst, int e2, int e) {
    int i = blockIdx.x * blockDim.x + threadIdx.x;
    if (i < e2) {
        int2 s = ((const int2*)src)[i];
        int2 d = ((const int2*)dst)[i];
        if ((unsigned)d.x < NN && (unsigned)s.x < NN) {
            int pos = g_row_ptr[d.x] + atomicAdd(&g_cursor[d.x], 1);
            g_csr_src[pos] = s.x;
        }
        if ((unsigned)d.y < NN && (unsigned)s.y < NN) {
            int pos = g_row_ptr[d.y] + atomicAdd(&g_cursor[d.y], 1);
            g_csr_src[pos] = s.y;
        }
    } else if (i == e2 && (e & 1)) {
        int s = src[e - 1], d = dst[e - 1];
        if ((unsigned)d < NN && (unsigned)s < NN) {
            int pos = g_row_ptr[d] + atomicAdd(&g_cursor[d], 1);
            g_csr_src[pos] = s;
        }
    }
}

// ---------------- SpMM 1 (fp16 gather, fp32 accumulate, fp16 out) ----------------
// warp per dst row, 4-edge unroll
__global__ void k_spmm1(int n) {
    int w = (blockIdx.x * blockDim.x + threadIdx.x) >> 5;
    int lane = threadIdx.x & 31;
    if (w >= n) return;
    int beg = g_row_ptr[w];
    int end = g_row_ptr[w + 1];
    const uint2* eh = (const uint2*)g_emb_h;   // row = 32 uint2
    float4 acc = make_float4(0.f, 0.f, 0.f, 0.f);
    int ed = beg;
    for (; ed + 3 < end; ed += 4) {
        int s0 = g_csr_src[ed];
        int s1 = g_csr_src[ed + 1];
        int s2 = g_csr_src[ed + 2];
        int s3 = g_csr_src[ed + 3];
        uint2 v0 = eh[(size_t)s0 * 32 + lane];
        uint2 v1 = eh[(size_t)s1 * 32 + lane];
        uint2 v2 = eh[(size_t)s2 * 32 + lane];
        uint2 v3 = eh[(size_t)s3 * 32 + lane];
        float2 a0 = __half22float2(*(__half2*)&v0.x), b0 = __half22float2(*(__half2*)&v0.y);
        float2 a1 = __half22float2(*(__half2*)&v1.x), b1 = __half22float2(*(__half2*)&v1.y);
        float2 a2 = __half22float2(*(__half2*)&v2.x), b2 = __half22float2(*(__half2*)&v2.y);
        float2 a3 = __half22float2(*(__half2*)&v3.x), b3 = __half22float2(*(__half2*)&v3.y);
        acc.x += (a0.x + a1.x) + (a2.x + a3.x);
        acc.y += (a0.y + a1.y) + (a2.y + a3.y);
        acc.z += (b0.x + b1.x) + (b2.x + b3.x);
        acc.w += (b0.y + b1.y) + (b2.y + b3.y);
    }
    for (; ed < end; ed++) {
        int s0 = g_csr_src[ed];
        uint2 v0 = eh[(size_t)s0 * 32 + lane];
        float2 a0 = __half22float2(*(__half2*)&v0.x);
        float2 b0 = __half22float2(*(__half2*)&v0.y);
        acc.x += a0.x; acc.y += a0.y; acc.z += b0.x; acc.w += b0.y;
    }
    float nd = g_norm_dst[w];
    uint2 o;
    *(__half2*)&o.x = __floats2half2_rn(acc.x * nd, acc.y * nd);
    *(__half2*)&o.y = __floats2half2_rn(acc.z * nd, acc.w * nd);
    ((uint2*)g_agg_h)[(size_t)w * 32 + lane] = o;
}

// ---------------- fused GEMM via HMMA (mma.sync m16n8k16) ----------------
__global__ void __launch_bounds__(256)
k_gemm_mma(const float* __restrict__ W1, const float* __restrict__ b1,
           const float* __restrict__ W2, int n) {
    __shared__ __half As[128 * APAD];    // 34.8KB
    __shared__ __half Wts[128 * WPAD];   // 10.2KB, [n][k] transposed chunks
    __shared__ float b1s[128];

    const int tid = threadIdx.x;
    const int lane = tid & 31;
    const int wid = tid >> 5;
    const int row0 = blockIdx.x * 128;
    const int m0 = wid * 16;
    const int r = lane >> 2;          // 0..7
    const int qc = (lane & 3) * 2;    // 0,2,4,6

    // load A tile (fp16, from g_agg_h), zero-pad OOB rows
    for (int i = tid; i < 128 * 32; i += 256) {
        int row = i >> 5, q = i & 31;
        int gr = row0 + row;
        uint2 v = make_uint2(0u, 0u);
        if (gr < n) v = ((const uint2*)g_agg_h)[(size_t)gr * 32 + q];
        *(uint2*)&As[row * APAD + q * 4] = v;
    }
    if (tid < 128) b1s[tid] = b1[tid];

    // ---- phase 1: 16x128 per warp, K=128 ----
    float acc[16][4];
#pragma unroll
    for (int t2 = 0; t2 < 16; t2++)
#pragma unroll
        for (int j = 0; j < 4; j++) acc[t2][j] = 0.f;

    for (int kc = 0; kc < 4; kc++) {
        __syncthreads();
        for (int i = tid; i < 32 * 128; i += 256) {
            int kl = i >> 7, nn = i & 127;
            Wts[nn * WPAD + kl] = __float2half(W1[(kc * 32 + kl) * 128 + nn]);
        }
        __syncthreads();
#pragma unroll
        for (int ks = 0; ks < 2; ks++) {
            int kb = kc * 32 + ks * 16;
            uint32_t a0 = *(uint32_t*)&As[(m0 + r) * APAD + kb + qc];
            uint32_t a1 = *(uint32_t*)&As[(m0 + r + 8) * APAD + kb + qc];
            uint32_t a2 = *(uint32_t*)&As[(m0 + r) * APAD + kb + qc + 8];
            uint32_t a3 = *(uint32_t*)&As[(m0 + r + 8) * APAD + kb + qc + 8];
            int kw = ks * 16;
#pragma unroll
            for (int nt = 0; nt < 16; nt++) {
                uint32_t b0 = *(uint32_t*)&Wts[(nt * 8 + r) * WPAD + kw + qc];
                uint32_t b1f = *(uint32_t*)&Wts[(nt * 8 + r) * WPAD + kw + qc + 8];
                MMA16816(acc[nt][0], acc[nt][1], acc[nt][2], acc[nt][3],
                         a0, a1, a2, a3, b0, b1f);
            }
        }
    }

    // epilogue 1: relu + bias, write h1 fp16 into As (own rows only)
#pragma unroll
    for (int nt = 0; nt < 16; nt++) {
        int c = nt * 8 + qc;
        float x0 = fmaxf(acc[nt][0] + b1s[c],     0.f);
        float x1 = fmaxf(acc[nt][1] + b1s[c + 1], 0.f);
        float x2 = fmaxf(acc[nt][2] + b1s[c],     0.f);
        float x3 = fmaxf(acc[nt][3] + b1s[c + 1], 0.f);
        *(__half2*)&As[(m0 + r) * APAD + c]     = __floats2half2_rn(x0, x1);
        *(__half2*)&As[(m0 + r + 8) * APAD + c] = __floats2half2_rn(x2, x3);
    }

    // ---- phase 2: 16x64 per warp, K=128 ----
    float acc2[8][4];
#pragma unroll
    for (int t2 = 0; t2 < 8; t2++)
#pragma unroll
        for (int j = 0; j < 4; j++) acc2[t2][j] = 0.f;

    for (int kc = 0; kc < 4; kc++) {
        __syncthreads();
        for (int i = tid; i < 32 * 64; i += 256) {
            int kl = i >> 6, nn = i & 63;
            Wts[nn * WPAD + kl] = __float2half(W2[(kc * 32 + kl) * 64 + nn]);
        }
        __syncthreads();
#pragma unroll
        for (int ks = 0; ks < 2; ks++) {
            int kb = kc * 32 + ks * 16;
            uint32_t a0 = *(uint32_t*)&As[(m0 + r) * APAD + kb + qc];
            uint32_t a1 = *(uint32_t*)&As[(m0 + r + 8) * APAD + kb + qc];
            uint32_t a2 = *(uint32_t*)&As[(m0 + r) * APAD + kb + qc + 8];
            uint32_t a3 = *(uint32_t*)&As[(m0 + r + 8) * APAD + kb + qc + 8];
            int kw = ks * 16;
#pragma unroll
            for (int nt = 0; nt < 8; nt++) {
                uint32_t b0 = *(uint32_t*)&Wts[(nt * 8 + r) * WPAD + kw + qc];
                uint32_t b1f = *(uint32_t*)&Wts[(nt * 8 + r) * WPAD + kw + qc + 8];
                MMA16816(acc2[nt][0], acc2[nt][1], acc2[nt][2], acc2[nt][3],
                         a0, a1, a2, a3, b0, b1f);
            }
        }
    }

    // epilogue 2: * norm_src, fp16 store
    {
        int gr0 = row0 + m0 + r;
        int gr1 = gr0 + 8;
        float ns0 = (gr0 < n) ? g_norm_src[gr0] : 0.f;
        float ns1 = (gr1 < n) ? g_norm_src[gr1] : 0.f;
#pragma unroll
        for (int nt = 0; nt < 8; nt++) {
            int c = nt * 8 + qc;   // even
            if (gr0 < n)
                g_t_h[(size_t)gr0 * 32 + (c >> 1)] =
                    __floats2half2_rn(acc2[nt][0] * ns0, acc2[nt][1] * ns0);
            if (gr1 < n)
                g_t_h[(size_t)gr1 * 32 + (c >> 1)] =
                    __floats2half2_rn(acc2[nt][2] * ns1, acc2[nt][3] * ns1);
        }
    }
}

// ---------------- SpMM 2 (fp16 gather, 4-edge unroll) ----------------
__global__ void k_spmm2(const float* __restrict__ b2, float* __restrict__ out, int n) {
    int w = (blockIdx.x * blockDim.x + threadIdx.x) >> 5;
    int lane = threadIdx.x & 31;
    if (w >= n) return;
    int beg = g_row_ptr[w];
    int end = g_row_ptr[w + 1];
    float2 acc = make_float2(0.f, 0.f);
    int ed = beg;
    for (; ed + 3 < end; ed += 4) {
        int s0 = g_csr_src[ed];
        int s1 = g_csr_src[ed + 1];
        int s2 = g_csr_src[ed + 2];
        int s3 = g_csr_src[ed + 3];
        float2 v0 = __half22float2(g_t_h[(size_t)s0 * 32 + lane]);
        float2 v1 = __half22float2(g_t_h[(size_t)s1 * 32 + lane]);
        float2 v2 = __half22float2(g_t_h[(size_t)s2 * 32 + lane]);
        float2 v3 = __half22float2(g_t_h[(size_t)s3 * 32 + lane]);
        acc.x += (v0.x + v1.x) + (v2.x + v3.x);
        acc.y += (v0.y + v1.y) + (v2.y + v3.y);
    }
    for (; ed < end; ed++) {
        int s0 = g_csr_src[ed];
        float2 v0 = __half22float2(g_t_h[(size_t)s0 * 32 + lane]);
        acc.x += v0.x;
        acc.y += v0.y;
    }
    float nd = g_norm_dst[w];
    float2 bb = ((const float2*)b2)[lane];
    float2 o;
    o.x = fmaf(acc.x, nd, bb.x);
    o.y = fmaf(acc.y, nd, bb.y);
    ((float2*)out)[(size_t)w * 32 + lane] = o;
}

// ---------------- launch ----------------
extern "C" void kernel_launch(void* const* d_in, const int* in_sizes, int n_in,
                              void* d_out, int out_size) {
    const int* src = (const int*)d_in[1];
    const int* dst = (const int*)d_in[2];
    const float* emb = (const float*)d_in[3];
    const float* W1  = (const float*)d_in[4];
    const float* b1  = (const float*)d_in[5];
    const float* W2  = (const float*)d_in[6];
    const float* b2  = (const float*)d_in[7];
    float* out = (float*)d_out;

    const int n = in_sizes[0];
    const int e = in_sizes[1];
    const int e2 = e >> 1;

    k_zero<<<(n + 255) / 256, 256>>>(n);
    k_degree<<<(e2 + 256) / 256, 256>>>(src, dst, e2, e);
    k_scan_partial<<<SCAN_NB, 256>>>(n);     // also computes norms
    k_prep<<<(n * 16 + 255) / 256, 256>>>(emb, n * 16);
    k_scan_blk<<<1, 128>>>(n, e);
    k_scan_final<<<SCAN_NB, 256>>>(n);
    k_fill<<<(e2 + 256) / 256, 256>>>(src, dst, e2, e);

    int warps_grid = (n * 32 + 255) / 256;
    k_spmm1<<<warps_grid, 256>>>(n);
    k_gemm_mma<<<(n + 127) / 128, 256>>>(W1, b1, W2, n);
    k_spmm2<<<warps_grid, 256>>>(b2, out, n);
}

// round 11
// speedup vs baseline: 1.2133x; 1.0022x over previous
#include <cuda_runtime.h>
#include <cuda_fp16.h>
#include <cstdint>

#define NN 100000
#define NE 1600000
#define SCAN_TILE 1024
#define SCAN_NB ((NN + SCAN_TILE - 1) / SCAN_TILE)   // 98

#define APAD 136   // As row stride (halves)
#define WPAD 40    // Wts row stride (halves)

// m16n8k16 fp16 MMA, fp32 accumulate (sm_80+ PTX, works on compute_103)
#define MMA16816(c0, c1, c2, c3, a0, a1, a2, a3, b0, b1) \
    asm volatile("mma.sync.aligned.m16n8k16.row.col.f32.f16.f16.f32 " \
        "{%0,%1,%2,%3}, {%4,%5,%6,%7}, {%8,%9}, {%0,%1,%2,%3};" \
        : "+f"(c0), "+f"(c1), "+f"(c2), "+f"(c3) \
        : "r"(a0), "r"(a1), "r"(a2), "r"(a3), "r"(b0), "r"(b1))

// ---------------- device scratch ----------------
__device__ int     g_deg_in[NN];
__device__ int     g_deg_out[NN];
__device__ int     g_cursor[NN];
__device__ float   g_norm_src[NN];
__device__ float   g_norm_dst[NN];
__device__ int     g_row_ptr[NN + 1];
__device__ int     g_csr_src[NE];
__device__ int     g_blk_sum[SCAN_NB];
__device__ int     g_blk_off[SCAN_NB];
__device__ __half2 g_emb_h[(size_t)NN * 64];   // emb * norm_src, fp16
__device__ __half2 g_agg_h[(size_t)NN * 64];   // spmm1 result, fp16
__device__ __half2 g_t_h[(size_t)NN * 32];     // (h1@W2)*norm_src, fp16

// ---------------- setup ----------------
__global__ void k_zero(int n) {
    int i = blockIdx.x * blockDim.x + threadIdx.x;
    if (i < n) { g_deg_in[i] = 0; g_deg_out[i] = 0; g_cursor[i] = 0; }
}

// 2 edges per thread, int2 loads
__global__ void k_degree(const int* __restrict__ src,
                         const int* __restrict__ dst, int e2, int e) {
    int i = blockIdx.x * blockDim.x + threadIdx.x;
    if (i < e2) {
        int2 s = ((const int2*)src)[i];
        int2 d = ((const int2*)dst)[i];
        if ((unsigned)s.x < NN) atomicAdd(&g_deg_out[s.x], 1);
        if ((unsigned)s.y < NN) atomicAdd(&g_deg_out[s.y], 1);
        if ((unsigned)d.x < NN) atomicAdd(&g_deg_in[d.x], 1);
        if ((unsigned)d.y < NN) atomicAdd(&g_deg_in[d.y], 1);
    } else if (i == e2 && (e & 1)) {
        int s = src[e - 1], d = dst[e - 1];
        if ((unsigned)s < NN) atomicAdd(&g_deg_out[s], 1);
        if ((unsigned)d < NN) atomicAdd(&g_deg_in[d], 1);
    }
}

// emb * norm_src -> half2; 8 floats per thread
__global__ void k_prep(const float* __restrict__ emb, int n16) {
    int i = blockIdx.x * blockDim.x + threadIdx.x;   // one per 8 feats
    if (i < n16) {
        int r = i >> 4;
        float4 v0 = ((const float4*)emb)[2 * i];
        float4 v1 = ((const float4*)emb)[2 * i + 1];
        float ns = g_norm_src[r];
        uint4 o;
        *(__half2*)&o.x = __floats2half2_rn(v0.x * ns, v0.y * ns);
        *(__half2*)&o.y = __floats2half2_rn(v0.z * ns, v0.w * ns);
        *(__half2*)&o.z = __floats2half2_rn(v1.x * ns, v1.y * ns);
        *(__half2*)&o.w = __floats2half2_rn(v1.z * ns, v1.w * ns);
        ((uint4*)g_emb_h)[i] = o;
    }
}

// ---------------- scan phase 1 + norm computation (fused) ----------------
__global__ void __launch_bounds__(256)
k_scan_partial(int n) {
    __shared__ int sm[256];
    int t = threadIdx.x;
    int base = blockIdx.x * SCAN_TILE + t * 4;
    int s = 0;
#pragma unroll
    for (int j = 0; j < 4; j++) {
        int i = base + j;
        if (i < n) {
            int din = g_deg_in[i];
            s += din;
            int dout = g_deg_out[i];
            if (dout < 1) dout = 1;
            if (din  < 1) din  = 1;
            g_norm_src[i] = rsqrtf((float)dout);
            g_norm_dst[i] = rsqrtf((float)din);
        }
    }
    sm[t] = s;
    __syncthreads();
    for (int off = 128; off > 0; off >>= 1) {
        if (t < off) sm[t] += sm[t + off];
        __syncthreads();
    }
    if (t == 0) g_blk_sum[blockIdx.x] = sm[0];
}

__global__ void __launch_bounds__(128)
k_scan_blk(int n, int e) {
    __shared__ int sm[128];
    int t = threadIdx.x;
    int v = (t < SCAN_NB) ? g_blk_sum[t] : 0;
    sm[t] = v;
    __syncthreads();
    for (int off = 1; off < 128; off <<= 1) {
        int add = 0;
        if (t >= off) add = sm[t - off];
        __syncthreads();
        sm[t] += add;
        __syncthreads();
    }
    if (t < SCAN_NB) g_blk_off[t] = sm[t] - v;
    if (t == 0) g_row_ptr[n] = e;
}

__global__ void __launch_bounds__(256)
k_scan_final(int n) {
    __shared__ int sm[256];
    int t = threadIdx.x;
    int base = blockIdx.x * SCAN_TILE + t * 4;
    int d[4];
    int s = 0;
#pragma unroll
    for (int j = 0; j < 4; j++) {
        int i = base + j;
        d[j] = (i < n) ? g_deg_in[i] : 0;
        s += d[j];
    }
    sm[t] = s;
    __syncthreads();
    for (int off = 1; off < 256; off <<= 1) {
        int add = 0;
        if (t >= off) add = sm[t - off];
        __syncthreads();
        sm[t] += add;
        __syncthreads();
    }
    int run = g_blk_off[blockIdx.x] + sm[t] - s;
#pragma unroll
    for (int j = 0; j < 4; j++) {
        int i = base + j;
        if (i < n) g_row_ptr[i] = run;
        run += d[j];
    }
}

// 2 edges per thread, int2 loads
__global__ void k_fill(const int* __restrict__ src,
                       const int* __restrict__ dst, int e2, int e) {
    int i = blockIdx.x * blockDim.x + threadIdx.x;
    if (i < e2) {
        int2 s = ((const int2*)src)[i];
        int2 d = ((const int2*)dst)[i];
        if ((unsigned)d.x < NN && (unsigned)s.x < NN) {
            int pos = g_row_ptr[d.x] + atomicAdd(&g_cursor[d.x], 1);
            g_csr_src[pos] = s.x;
        }
        if ((unsigned)d.y < NN && (unsigned)s.y < NN) {
            int pos = g_row_ptr[d.y] + atomicAdd(&g_cursor[d.y], 1);
            g_csr_src[pos] = s.y;
        }
    } else if (i == e2 && (e & 1)) {
        int s = src[e - 1], d = dst[e - 1];
        if ((unsigned)d < NN && (unsigned)s < NN) {
            int pos = g_row_ptr[d] + atomicAdd(&g_cursor[d], 1);
            g_csr_src[pos] = s;
        }
    }
}

// ---------------- SpMM 1 (fp16 gather, fp32 accumulate, fp16 out) ----------------
// warp per dst row in [rbeg, rend), 4-edge unroll
__global__ void k_spmm1(int rbeg, int rend) {
    int w = rbeg + ((blockIdx.x * blockDim.x + threadIdx.x) >> 5);
    int lane = threadIdx.x & 31;
    if (w >= rend) return;
    int beg = g_row_ptr[w];
    int end = g_row_ptr[w + 1];
    const uint2* eh = (const uint2*)g_emb_h;   // row = 32 uint2
    float4 acc = make_float4(0.f, 0.f, 0.f, 0.f);
    int ed = beg;
    for (; ed + 3 < end; ed += 4) {
        int s0 = g_csr_src[ed];
        int s1 = g_csr_src[ed + 1];
        int s2 = g_csr_src[ed + 2];
        int s3 = g_csr_src[ed + 3];
        uint2 v0 = eh[(size_t)s0 * 32 + lane];
        uint2 v1 = eh[(size_t)s1 * 32 + lane];
        uint2 v2 = eh[(size_t)s2 * 32 + lane];
        uint2 v3 = eh[(size_t)s3 * 32 + lane];
        float2 a0 = __half22float2(*(__half2*)&v0.x), b0 = __half22float2(*(__half2*)&v0.y);
        float2 a1 = __half22float2(*(__half2*)&v1.x), b1 = __half22float2(*(__half2*)&v1.y);
        float2 a2 = __half22float2(*(__half2*)&v2.x), b2 = __half22float2(*(__half2*)&v2.y);
        float2 a3 = __half22float2(*(__half2*)&v3.x), b3 = __half22float2(*(__half2*)&v3.y);
        acc.x += (a0.x + a1.x) + (a2.x + a3.x);
        acc.y += (a0.y + a1.y) + (a2.y + a3.y);
        acc.z += (b0.x + b1.x) + (b2.x + b3.x);
        acc.w += (b0.y + b1.y) + (b2.y + b3.y);
    }
    for (; ed < end; ed++) {
        int s0 = g_csr_src[ed];
        uint2 v0 = eh[(size_t)s0 * 32 + lane];
        float2 a0 = __half22float2(*(__half2*)&v0.x);
        float2 b0 = __half22float2(*(__half2*)&v0.y);
        acc.x += a0.x; acc.y += a0.y; acc.z += b0.x; acc.w += b0.y;
    }
    float nd = g_norm_dst[w];
    uint2 o;
    *(__half2*)&o.x = __floats2half2_rn(acc.x * nd, acc.y * nd);
    *(__half2*)&o.y = __floats2half2_rn(acc.z * nd, acc.w * nd);
    ((uint2*)g_agg_h)[(size_t)w * 32 + lane] = o;
}

// ---------------- fused GEMM via HMMA (mma.sync m16n8k16) ----------------
// rows [rbeg + blockIdx.x*128, ...), bounded by n
__global__ void __launch_bounds__(256)
k_gemm_mma(const float* __restrict__ W1, const float* __restrict__ b1,
           const float* __restrict__ W2, int rbeg, int n) {
    __shared__ __half As[128 * APAD];    // 34.8KB
    __shared__ __half Wts[128 * WPAD];   // 10.2KB, [n][k] transposed chunks
    __shared__ float b1s[128];

    const int tid = threadIdx.x;
    const int lane = tid & 31;
    const int wid = tid >> 5;
    const int row0 = rbeg + blockIdx.x * 128;
    const int m0 = wid * 16;
    const int r = lane >> 2;          // 0..7
    const int qc = (lane & 3) * 2;    // 0,2,4,6

    // load A tile (fp16, from g_agg_h), zero-pad OOB rows
    for (int i = tid; i < 128 * 32; i += 256) {
        int row = i >> 5, q = i & 31;
        int gr = row0 + row;
        uint2 v = make_uint2(0u, 0u);
        if (gr < n) v = ((const uint2*)g_agg_h)[(size_t)gr * 32 + q];
        *(uint2*)&As[row * APAD + q * 4] = v;
    }
    if (tid < 128) b1s[tid] = b1[tid];

    // ---- phase 1: 16x128 per warp, K=128 ----
    float acc[16][4];
#pragma unroll
    for (int t2 = 0; t2 < 16; t2++)
#pragma unroll
        for (int j = 0; j < 4; j++) acc[t2][j] = 0.f;

    for (int kc = 0; kc < 4; kc++) {
        __syncthreads();
        for (int i = tid; i < 32 * 128; i += 256) {
            int kl = i >> 7, nn = i & 127;
            Wts[nn * WPAD + kl] = __float2half(W1[(kc * 32 + kl) * 128 + nn]);
        }
        __syncthreads();
#pragma unroll
        for (int ks = 0; ks < 2; ks++) {
            int kb = kc * 32 + ks * 16;
            uint32_t a0 = *(uint32_t*)&As[(m0 + r) * APAD + kb + qc];
            uint32_t a1 = *(uint32_t*)&As[(m0 + r + 8) * APAD + kb + qc];
            uint32_t a2 = *(uint32_t*)&As[(m0 + r) * APAD + kb + qc + 8];
            uint32_t a3 = *(uint32_t*)&As[(m0 + r + 8) * APAD + kb + qc + 8];
            int kw = ks * 16;
#pragma unroll
            for (int nt = 0; nt < 16; nt++) {
                uint32_t b0 = *(uint32_t*)&Wts[(nt * 8 + r) * WPAD + kw + qc];
                uint32_t b1f = *(uint32_t*)&Wts[(nt * 8 + r) * WPAD + kw + qc + 8];
                MMA16816(acc[nt][0], acc[nt][1], acc[nt][2], acc[nt][3],
                         a0, a1, a2, a3, b0, b1f);
            }
        }
    }

    // epilogue 1: relu + bias, write h1 fp16 into As (own rows only)
#pragma unroll
    for (int nt = 0; nt < 16; nt++) {
        int c = nt * 8 + qc;
        float x0 = fmaxf(acc[nt][0] + b1s[c],     0.f);
        float x1 = fmaxf(acc[nt][1] + b1s[c + 1], 0.f);
        float x2 = fmaxf(acc[nt][2] + b1s[c],     0.f);
        float x3 = fmaxf(acc[nt][3] + b1s[c + 1], 0.f);
        *(__half2*)&As[(m0 + r) * APAD + c]     = __floats2half2_rn(x0, x1);
        *(__half2*)&As[(m0 + r + 8) * APAD + c] = __floats2half2_rn(x2, x3);
    }

    // ---- phase 2: 16x64 per warp, K=128 ----
    float acc2[8][4];
#pragma unroll
    for (int t2 = 0; t2 < 8; t2++)
#pragma unroll
        for (int j = 0; j < 4; j++) acc2[t2][j] = 0.f;

    for (int kc = 0; kc < 4; kc++) {
        __syncthreads();
        for (int i = tid; i < 32 * 64; i += 256) {
            int kl = i >> 6, nn = i & 63;
            Wts[nn * WPAD + kl] = __float2half(W2[(kc * 32 + kl) * 64 + nn]);
        }
        __syncthreads();
#pragma unroll
        for (int ks = 0; ks < 2; ks++) {
            int kb = kc * 32 + ks * 16;
            uint32_t a0 = *(uint32_t*)&As[(m0 + r) * APAD + kb + qc];
            uint32_t a1 = *(uint32_t*)&As[(m0 + r + 8) * APAD + kb + qc];
            uint32_t a2 = *(uint32_t*)&As[(m0 + r) * APAD + kb + qc + 8];
            uint32_t a3 = *(uint32_t*)&As[(m0 + r + 8) * APAD + kb + qc + 8];
            int kw = ks * 16;
#pragma unroll
            for (int nt = 0; nt < 8; nt++) {
                uint32_t b0 = *(uint32_t*)&Wts[(nt * 8 + r) * WPAD + kw + qc];
                uint32_t b1f = *(uint32_t*)&Wts[(nt * 8 + r) * WPAD + kw + qc + 8];
                MMA16816(acc2[nt][0], acc2[nt][1], acc2[nt][2], acc2[nt][3],
                         a0, a1, a2, a3, b0, b1f);
            }
        }
    }

    // epilogue 2: * norm_src, fp16 store
    {
        int gr0 = row0 + m0 + r;
        int gr1 = gr0 + 8;
        float ns0 = (gr0 < n) ? g_norm_src[gr0] : 0.f;
        float ns1 = (gr1 < n) ? g_norm_src[gr1] : 0.f;
#pragma unroll
        for (int nt = 0; nt < 8; nt++) {
            int c = nt * 8 + qc;   // even
            if (gr0 < n)
                g_t_h[(size_t)gr0 * 32 + (c >> 1)] =
                    __floats2half2_rn(acc2[nt][0] * ns0, acc2[nt][1] * ns0);
            if (gr1 < n)
                g_t_h[(size_t)gr1 * 32 + (c >> 1)] =
                    __floats2half2_rn(acc2[nt][2] * ns1, acc2[nt][3] * ns1);
        }
    }
}

// ---------------- SpMM 2 (fp16 gather, 4-edge unroll) ----------------
__global__ void k_spmm2(const float* __restrict__ b2, float* __restrict__ out, int n) {
    int w = (blockIdx.x * blockDim.x + threadIdx.x) >> 5;
    int lane = threadIdx.x & 31;
    if (w >= n) return;
    int beg = g_row_ptr[w];
    int end = g_row_ptr[w + 1];
    float2 acc = make_float2(0.f, 0.f);
    int ed = beg;
    for (; ed + 3 < end; ed += 4) {
        int s0 = g_csr_src[ed];
        int s1 = g_csr_src[ed + 1];
        int s2 = g_csr_src[ed + 2];
        int s3 = g_csr_src[ed + 3];
        float2 v0 = __half22float2(g_t_h[(size_t)s0 * 32 + lane]);
        float2 v1 = __half22float2(g_t_h[(size_t)s1 * 32 + lane]);
        float2 v2 = __half22float2(g_t_h[(size_t)s2 * 32 + lane]);
        float2 v3 = __half22float2(g_t_h[(size_t)s3 * 32 + lane]);
        acc.x += (v0.x + v1.x) + (v2.x + v3.x);
        acc.y += (v0.y + v1.y) + (v2.y + v3.y);
    }
    for (; ed < end; ed++) {
        int s0 = g_csr_src[ed];
        float2 v0 = __half22float2(g_t_h[(size_t)s0 * 32 + lane]);
        acc.x += v0.x;
        acc.y += v0.y;
    }
    float nd = g_norm_dst[w];
    float2 bb = ((const float2*)b2)[lane];
    float2 o;
    o.x = fmaf(acc.x, nd, bb.x);
    o.y = fmaf(acc.y, nd, bb.y);
    ((float2*)out)[(size_t)w * 32 + lane] = o;
}

// ---------------- launch (fork/join stream pipeline, graph-capturable) ----------------
extern "C" void kernel_launch(void* const* d_in, const int* in_sizes, int n_in,
                              void* d_out, int out_size) {
    const int* src = (const int*)d_in[1];
    const int* dst = (const int*)d_in[2];
    const float* emb = (const float*)d_in[3];
    const float* W1  = (const float*)d_in[4];
    const float* b1  = (const float*)d_in[5];
    const float* W2  = (const float*)d_in[6];
    const float* b2  = (const float*)d_in[7];
    float* out = (float*)d_out;

    const int n = in_sizes[0];
    const int e = in_sizes[1];
    const int e2 = e >> 1;

    // host-side stream/event objects, created once (no device memory involved)
    static cudaStream_t s1 = nullptr;
    static cudaEvent_t evA = nullptr, evP = nullptr, ev1 = nullptr, evG0 = nullptr;
    if (!s1) {
        cudaStreamCreateWithFlags(&s1, cudaStreamNonBlocking);
        cudaEventCreateWithFlags(&evA, cudaEventDisableTiming);
        cudaEventCreateWithFlags(&evP, cudaEventDisableTiming);
        cudaEventCreateWithFlags(&ev1, cudaEventDisableTiming);
        cudaEventCreateWithFlags(&evG0, cudaEventDisableTiming);
    }

    // row split for the spmm1/gemm pipeline (multiple of 128)
    const int nb_total = (n + 127) / 128;
    const int nb0 = nb_total / 2;
    const int nh = nb0 * 128;                      // rows in half 0
    const int nb1 = nb_total - nb0;

    // ---- main stream (0): degree/CSR chain ----
    k_zero<<<(n + 255) / 256, 256>>>(n);
    k_degree<<<(e2 + 256) / 256, 256>>>(src, dst, e2, e);
    k_scan_partial<<<SCAN_NB, 256>>>(n);           // also computes norms
    cudaEventRecord(evA, 0);

    // ---- fork: prep on s1 (needs only norm_src) ----
    cudaStreamWaitEvent(s1, evA, 0);
    k_prep<<<(n * 16 + 255) / 256, 256, 0, s1>>>(emb, n * 16);
    cudaEventRecord(evP, s1);

    // ---- main stream continues CSR build concurrently ----
    k_scan_blk<<<1, 128>>>(n, e);
    k_scan_final<<<SCAN_NB, 256>>>(n);
    k_fill<<<(e2 + 256) / 256, 256>>>(src, dst, e2, e);

    // join prep before spmm1
    cudaStreamWaitEvent(0, evP, 0);

    // ---- spmm1 half 0, then pipeline: spmm1 half1 (s0) || gemm half0 (s1) ----
    k_spmm1<<<(nh * 32 + 255) / 256, 256>>>(0, nh);
    cudaEventRecord(ev1, 0);

    k_spmm1<<<((n - nh) * 32 + 255) / 256, 256>>>(nh, n);

    cudaStreamWaitEvent(s1, ev1, 0);
    k_gemm_mma<<<nb0, 256, 0, s1>>>(W1, b1, W2, 0, n);
    cudaEventRecord(evG0, s1);

    k_gemm_mma<<<nb1, 256>>>(W1, b1, W2, nh, n);

    // join gemm half0 before spmm2
    cudaStreamWaitEvent(0, evG0, 0);
    k_spmm2<<<(n * 32 + 255) / 256, 256>>>(b2, out, n);
}